// round 5
// baseline (speedup 1.0000x reference)
#include <cuda_runtime.h>
#include <cuda_bf16.h>
#include <cstdint>

// Problem constants
#define B_  32
#define Q_  500
#define T_  128
#define NC_ 80
#define BQ_ (B_ * B_ == 0 ? 0 : B_ * Q_)     // 16000
#define BT_ (B_ * T_)     // 4096

#define TR 32             // tile rows
#define TC 128            // tile cols

// ---------------------------------------------------------------------------
// FFMA-imm helpers: rt_SMSP=1 (2x throughput vs FADD rt=2 on sm_103a).
// Immediates are perturbed by 1 ulp so ptxas cannot fold them back to FADD.
// Error contribution ~1.2e-7 relative per op -- budget is 1e-3.
// ---------------------------------------------------------------------------
__device__ __forceinline__ float fadd1(float a, float c) {   // ~ a + c
    float d; asm("fma.rn.f32 %0, %1, 0f3F800001, %2;" : "=f"(d) : "f"(a), "f"(c)); return d;
}
__device__ __forceinline__ float fsub1(float a, float b) {   // ~ a - b
    float d; asm("fma.rn.f32 %0, %1, 0fBF800001, %2;" : "=f"(d) : "f"(b), "f"(a)); return d;
}
__device__ __forceinline__ float fnma2(float x, float c) {   // ~ c - 2*x
    float d; asm("fma.rn.f32 %0, %1, 0fC0000001, %2;" : "=f"(d) : "f"(x), "f"(c)); return d;
}

// Scratch (device globals: allocation-free rule)
__device__ float g_prob[BQ_ * NC_];    // pv = 2 - 2*softmax, [row][cls]
__device__ float g_row[BQ_ * 12];      // per-query: 5*nx1,5*ny1,5*nx2,5*ny2, x1,y1,x2,y2, w,h,area, pad
__device__ float g_col[BT_ * 12];      // per-target: same layout
__device__ int   g_cls[BT_];           // target class ids

// ---------------------------------------------------------------------------
// Prep 1: softmax (stored as pv = 2 - 2*p) + per-query box precompute.
// ---------------------------------------------------------------------------
__global__ void prep_rows_kernel(const float* __restrict__ logits,
                                 const float* __restrict__ boxes,
                                 const float* __restrict__ img_sz)
{
    int row  = blockIdx.x * 8 + (threadIdx.x >> 5);
    int lane = threadIdx.x & 31;

    const float* lg = logits + (size_t)row * NC_;
    float v0 = lg[lane];
    float v1 = lg[lane + 32];
    float v2 = (lane < 16) ? lg[lane + 64] : -3.4e38f;

    float m = fmaxf(v0, fmaxf(v1, v2));
    #pragma unroll
    for (int o = 16; o; o >>= 1) m = fmaxf(m, __shfl_xor_sync(0xffffffffu, m, o));

    float e0 = __expf(v0 - m);
    float e1 = __expf(v1 - m);
    float e2 = (lane < 16) ? __expf(v2 - m) : 0.f;
    float s = e0 + e1 + e2;
    #pragma unroll
    for (int o = 16; o; o >>= 1) s += __shfl_xor_sync(0xffffffffu, s, o);

    // pv = 2 - 2*p  (class cost + giou "+2" constant pre-folded)
    float ninv2 = __fdividef(-2.f, s);
    float* pr = g_prob + (size_t)row * NC_;
    pr[lane]      = fmaf(e0, ninv2, 2.f);
    pr[lane + 32] = fmaf(e1, ninv2, 2.f);
    if (lane < 16) pr[lane + 64] = fmaf(e2, ninv2, 2.f);

    if (lane == 0) {
        int b = row / Q_;
        const float* bx = boxes + (size_t)row * 4;
        float x1 = bx[0], y1 = bx[1], x2 = bx[2], y2 = bx[3];
        float s0 = img_sz[b * 4 + 0], s1 = img_sz[b * 4 + 1];
        float s2 = img_sz[b * 4 + 2], s3 = img_sz[b * 4 + 3];
        float w = x2 - x1, h = y2 - y1;
        float* r = g_row + row * 12;
        // normalized coords pre-scaled by COST_BBOX=5
        r[0] = __fdividef(5.f * x1, s0);
        r[1] = __fdividef(5.f * y1, s1);
        r[2] = __fdividef(5.f * x2, s2);
        r[3] = __fdividef(5.f * y2, s3);
        r[4] = x1; r[5] = y1; r[6] = x2; r[7] = y2;
        r[8] = w;  r[9] = h;  r[10] = w * h; r[11] = 0.f;
    }
}

// ---------------------------------------------------------------------------
// Prep 2: per-target box precompute (normalized pre-scaled by 5) + class id.
// ---------------------------------------------------------------------------
__global__ void prep_cols_kernel(const float* __restrict__ tboxes,
                                 const int*   __restrict__ tlabels,
                                 const float* __restrict__ img_sz_tgt)
{
    int j = blockIdx.x * blockDim.x + threadIdx.x;
    if (j >= BT_) return;

    const float* bx = tboxes + (size_t)j * 4;
    const float* sz = img_sz_tgt + (size_t)j * 4;
    float x1 = bx[0], y1 = bx[1], x2 = bx[2], y2 = bx[3];
    float w = x2 - x1, h = y2 - y1;
    float* c = g_col + j * 12;
    c[0] = __fdividef(5.f * x1, sz[0]);
    c[1] = __fdividef(5.f * y1, sz[1]);
    c[2] = __fdividef(5.f * x2, sz[2]);
    c[3] = __fdividef(5.f * y2, sz[3]);
    c[4] = x1; c[5] = y1; c[6] = x2; c[7] = y2;
    c[8] = w;  c[9] = h;  c[10] = w * h; c[11] = 0.f;

    g_cls[j] = tlabels[j];
}

// ---------------------------------------------------------------------------
// Main: cost matrix [BQ, BT]. 32x128 tile, thread = 4 rows x 4 cols.
// Adds/subs issued as FFMA-imm (rt=1); muls/fmas reg-form (rt=2); min/max on
// the idle alu pipe. fma-pipe slots: 44 -> 31 per element.
// ---------------------------------------------------------------------------
__global__ __launch_bounds__(256, 3)
void cost_kernel(float* __restrict__ out)
{
    __shared__ float sr[TR][13];        // row box data (broadcast reads)
    __shared__ float sc[TC][13];        // col box data (stride 13: conflict-free)
    __shared__ int   scls[TC];          // col class ids

    const int r0 = blockIdx.y * TR;
    const int c0 = blockIdx.x * TC;
    const int tid = threadIdx.x;

    for (int idx = tid; idx < TC; idx += 256) scls[idx] = g_cls[c0 + idx];
    for (int idx = tid; idx < TR * 12; idx += 256) {
        int e = idx / 12, f = idx % 12;
        sr[e][f] = g_row[(r0 + e) * 12 + f];
    }
    for (int idx = tid; idx < TC * 12; idx += 256) {
        int e = idx / 12, f = idx % 12;
        sc[e][f] = g_col[(c0 + e) * 12 + f];
    }
    __syncthreads();

    const int tc = tid & 31;       // column group (4 consecutive cols)
    const int tr = tid >> 5;       // row group (4 rows); constant per warp
    const int rloc = tr * 4;
    const int cloc = tc * 4;

    // Row data into registers
    float Rnx1[4], Rny1[4], Rnx2[4], Rny2[4];
    float Rx1[4], Ry1[4], Rx2[4], Ry2[4];
    float Rw[4], Rh[4], Ra[4];
    #pragma unroll
    for (int rr = 0; rr < 4; rr++) {
        Rnx1[rr] = sr[rloc + rr][0];
        Rny1[rr] = sr[rloc + rr][1];
        Rnx2[rr] = sr[rloc + rr][2];
        Rny2[rr] = sr[rloc + rr][3];
        Rx1[rr]  = sr[rloc + rr][4];
        Ry1[rr]  = sr[rloc + rr][5];
        Rx2[rr]  = sr[rloc + rr][6];
        Ry2[rr]  = sr[rloc + rr][7];
        Rw[rr]   = sr[rloc + rr][8];
        Rh[rr]   = sr[rloc + rr][9];
        Ra[rr]   = sr[rloc + rr][10];
    }

    // Per-thread class ids for the 4 columns
    int clsr[4];
    #pragma unroll
    for (int cc = 0; cc < 4; cc++) clsr[cc] = scls[cloc + cc];

    const float* prow = g_prob + (size_t)(r0 + rloc) * NC_;

    float res[4][4];

    #pragma unroll
    for (int cc = 0; cc < 4; cc++) {
        const int c = cloc + cc;
        const float cnx1 = sc[c][0], cny1 = sc[c][1];
        const float cnx2 = sc[c][2], cny2 = sc[c][3];
        const float ctx1 = sc[c][4], cty1 = sc[c][5];
        const float ctx2 = sc[c][6], cty2 = sc[c][7];
        const float cwt  = sc[c][8], cht  = sc[c][9];
        const float cat  = sc[c][10];
        const int   cls  = clsr[cc];

        #pragma unroll
        for (int rr = 0; rr < 4; rr++) {
            // intersection extents (FMNMX -> alu pipe)
            float m2x = fminf(Rx2[rr], ctx2);
            float M1x = fmaxf(Rx1[rr], ctx1);
            float m2y = fminf(Ry2[rr], cty2);
            float M1y = fmaxf(Ry1[rr], cty1);
            float wrx = fsub1(m2x, M1x);               // rt1
            float wry = fsub1(m2y, M1y);               // rt1
            float iw  = fmaxf(wrx, 0.f);
            float ih  = fmaxf(wry, 0.f);
            // enclosing extents via max = sum - min identity
            float exs = fsub1(fadd1(Rw[rr], cwt), wrx);  // 2x rt1
            float eys = fsub1(fadd1(Rh[rr], cht), wry);  // 2x rt1
            float inter = iw * ih;                       // rt2
            float areae = exs * eys;                     // rt2
            float uni   = fsub1(fadd1(Ra[rr], cat), inter); // 2x rt1
            // giou terms with single fast division
            float num = fmaf(inter, areae, uni * uni);   // 2x rt2
            float den = uni * areae;                     // rt2

            // 5*L1 of normalized boxes (coords pre-scaled by 5)
            float d1 = fsub1(Rnx1[rr], cnx1);            // rt1 x4
            float d2 = fsub1(Rny1[rr], cny1);
            float d3 = fsub1(Rnx2[rr], cnx2);
            float d4 = fsub1(Rny2[rr], cny2);
            float s1 = fabsf(d1) + fabsf(d2);            // FADD.|.| rt2
            float s2 = fabsf(d3) + fabsf(d4);            // rt2
            float cb = fadd1(s1, s2);                    // rt1

            // pv = 2 - 2*p  (one LDG, all lanes on the same prob row)
            float pv = __ldg(&prow[rr * NC_ + cls]);

            // C = cb + pv - 2*(num/den)
            float base = fadd1(cb, pv);                  // rt1
            res[rr][cc] = fnma2(__fdividef(num, den), base); // MUFU+mul, rt1
        }
    }

    // Coalesced float4 stores (warp covers 512B contiguous per rr)
    #pragma unroll
    for (int rr = 0; rr < 4; rr++) {
        size_t i = (size_t)(r0 + rloc + rr);
        float4 v = make_float4(res[rr][0], res[rr][1], res[rr][2], res[rr][3]);
        *reinterpret_cast<float4*>(out + i * BT_ + c0 + cloc) = v;
    }
}

// ---------------------------------------------------------------------------
extern "C" void kernel_launch(void* const* d_in, const int* in_sizes, int n_in,
                              void* d_out, int out_size)
{
    const float* pred_logits  = (const float*)d_in[0];   // [B,Q,NC]
    const float* pred_boxes   = (const float*)d_in[1];   // [B,Q,4]
    const int*   tgt_labels   = (const int*)d_in[2];     // [B,T]
    const float* tgt_boxes    = (const float*)d_in[3];   // [B,T,4]
    const float* img_sz       = (const float*)d_in[4];   // [B,4]
    const float* img_sz_tgt   = (const float*)d_in[5];   // [B,T,4]
    float* out = (float*)d_out;

    prep_rows_kernel<<<BQ_ / 8, 256>>>(pred_logits, pred_boxes, img_sz);
    prep_cols_kernel<<<(BT_ + 255) / 256, 256>>>(tgt_boxes, tgt_labels, img_sz_tgt);

    dim3 grid(BT_ / TC, BQ_ / TR);   // (32, 500)
    cost_kernel<<<grid, 256>>>(out);
}

// round 6
// speedup vs baseline: 1.3519x; 1.3519x over previous
#include <cuda_runtime.h>
#include <cuda_bf16.h>
#include <cstdint>

// Problem constants
#define B_  32
#define Q_  500
#define T_  128
#define NC_ 80
#define BQ_ (B_ * Q_)     // 16000
#define BT_ (B_ * T_)     // 4096

#define TR 32             // tile rows
#define TC 128            // tile cols
#define SIDX(c) ((c) + ((c) >> 3))   // conflict-free float4 swizzle

// ---------------------------------------------------------------------------
// FFMA-imm helpers: rt_SMSP=1 (2x throughput vs FADD rt=2 on sm_103a).
// Immediates perturbed by 1 ulp so ptxas cannot fold them back to FADD.
// ---------------------------------------------------------------------------
__device__ __forceinline__ float fadd1(float a, float c) {   // ~ a + c
    float d; asm("fma.rn.f32 %0, %1, 0f3F800001, %2;" : "=f"(d) : "f"(a), "f"(c)); return d;
}
__device__ __forceinline__ float fsub1(float a, float b) {   // ~ a - b
    float d; asm("fma.rn.f32 %0, %1, 0fBF800001, %2;" : "=f"(d) : "f"(b), "f"(a)); return d;
}
__device__ __forceinline__ float fnma2(float x, float c) {   // ~ c - 2*x
    float d; asm("fma.rn.f32 %0, %1, 0fC0000001, %2;" : "=f"(d) : "f"(x), "f"(c)); return d;
}

// Scratch (device globals: allocation-free rule). SoA float4 layout.
__device__ float  g_prob[BQ_ * NC_];   // pv = 2 - 2*softmax, [row][cls]
__device__ float4 g_rowA[BQ_];         // 5*nx1, 5*ny1, 5*nx2, 5*ny2
__device__ float4 g_rowB[BQ_];         // x1, y1, x2, y2
__device__ float4 g_rowC[BQ_];         // w, h, area, 0
__device__ float4 g_colA[BT_];
__device__ float4 g_colB[BT_];
__device__ float4 g_colC[BT_];         // w, h, area, cls (int bits)

// ---------------------------------------------------------------------------
// Fused prep: blocks [0, BQ_/8) do softmax rows; blocks after do targets.
// ---------------------------------------------------------------------------
#define ROWBLKS (BQ_ / 8)   // 2000

__global__ void prep_kernel(const float* __restrict__ logits,
                            const float* __restrict__ boxes,
                            const float* __restrict__ img_sz,
                            const float* __restrict__ tboxes,
                            const int*   __restrict__ tlabels,
                            const float* __restrict__ img_sz_tgt)
{
    if (blockIdx.x < ROWBLKS) {
        // ---- per-query: softmax (stored as pv = 2-2p) + box precompute ----
        int row  = blockIdx.x * 8 + (threadIdx.x >> 5);
        int lane = threadIdx.x & 31;

        const float* lg = logits + (size_t)row * NC_;
        float v0 = lg[lane];
        float v1 = lg[lane + 32];
        float v2 = (lane < 16) ? lg[lane + 64] : -3.4e38f;

        float m = fmaxf(v0, fmaxf(v1, v2));
        #pragma unroll
        for (int o = 16; o; o >>= 1) m = fmaxf(m, __shfl_xor_sync(0xffffffffu, m, o));

        float e0 = __expf(v0 - m);
        float e1 = __expf(v1 - m);
        float e2 = (lane < 16) ? __expf(v2 - m) : 0.f;
        float s = e0 + e1 + e2;
        #pragma unroll
        for (int o = 16; o; o >>= 1) s += __shfl_xor_sync(0xffffffffu, s, o);

        float ninv2 = __fdividef(-2.f, s);
        float* pr = g_prob + (size_t)row * NC_;
        pr[lane]      = fmaf(e0, ninv2, 2.f);
        pr[lane + 32] = fmaf(e1, ninv2, 2.f);
        if (lane < 16) pr[lane + 64] = fmaf(e2, ninv2, 2.f);

        if (lane == 0) {
            int b = row / Q_;
            const float* bx = boxes + (size_t)row * 4;
            float x1 = bx[0], y1 = bx[1], x2 = bx[2], y2 = bx[3];
            float s0 = img_sz[b * 4 + 0], s1 = img_sz[b * 4 + 1];
            float s2 = img_sz[b * 4 + 2], s3 = img_sz[b * 4 + 3];
            float w = x2 - x1, h = y2 - y1;
            g_rowA[row] = make_float4(__fdividef(5.f * x1, s0),
                                      __fdividef(5.f * y1, s1),
                                      __fdividef(5.f * x2, s2),
                                      __fdividef(5.f * y2, s3));
            g_rowB[row] = make_float4(x1, y1, x2, y2);
            g_rowC[row] = make_float4(w, h, w * h, 0.f);
        }
    } else {
        // ---- per-target: box precompute + class id ----
        int j = (blockIdx.x - ROWBLKS) * blockDim.x + threadIdx.x;
        if (j >= BT_) return;

        const float* bx = tboxes + (size_t)j * 4;
        const float* sz = img_sz_tgt + (size_t)j * 4;
        float x1 = bx[0], y1 = bx[1], x2 = bx[2], y2 = bx[3];
        float w = x2 - x1, h = y2 - y1;
        g_colA[j] = make_float4(__fdividef(5.f * x1, sz[0]),
                                __fdividef(5.f * y1, sz[1]),
                                __fdividef(5.f * x2, sz[2]),
                                __fdividef(5.f * y2, sz[3]));
        g_colB[j] = make_float4(x1, y1, x2, y2);
        g_colC[j] = make_float4(w, h, w * h, __int_as_float(tlabels[j]));
    }
}

// ---------------------------------------------------------------------------
// Main: cost matrix [BQ, BT]. 32x128 tile, thread = 4 rows x 4 cols.
// Col data: SoA float4 in shared, add-swizzled -> conflict-free LDS.128
// (crossbar cost per warp-tile: 176 cyc -> 48 cyc vs round 5).
// ---------------------------------------------------------------------------
__global__ __launch_bounds__(256, 3)
void cost_kernel(float* __restrict__ out)
{
    __shared__ float4 srA[TR], srB[TR], srC[TR];       // broadcast reads
    __shared__ float4 scA[TC + TC/8], scB[TC + TC/8], scC[TC + TC/8];

    const int r0 = blockIdx.y * TR;
    const int c0 = blockIdx.x * TC;
    const int tid = threadIdx.x;

    if (tid < TC) {
        int si = SIDX(tid);
        scA[si] = g_colA[c0 + tid];
        scB[si] = g_colB[c0 + tid];
        scC[si] = g_colC[c0 + tid];
    } else if (tid < TC + TR) {
        int r = tid - TC;
        srA[r] = g_rowA[r0 + r];
        srB[r] = g_rowB[r0 + r];
        srC[r] = g_rowC[r0 + r];
    }
    __syncthreads();

    const int tc = tid & 31;       // column group (4 consecutive cols)
    const int tr = tid >> 5;       // row group (4 rows); constant per warp
    const int rloc = tr * 4;
    const int cloc = tc * 4;

    // Row data into registers (broadcast LDS, N=1)
    float Rnx1[4], Rny1[4], Rnx2[4], Rny2[4];
    float Rx1[4], Ry1[4], Rx2[4], Ry2[4];
    float Rw[4], Rh[4], Ra[4];
    #pragma unroll
    for (int rr = 0; rr < 4; rr++) {
        float4 A = srA[rloc + rr];
        float4 Bv = srB[rloc + rr];
        float4 Cv = srC[rloc + rr];
        Rnx1[rr] = A.x;  Rny1[rr] = A.y;  Rnx2[rr] = A.z;  Rny2[rr] = A.w;
        Rx1[rr]  = Bv.x; Ry1[rr]  = Bv.y; Rx2[rr]  = Bv.z; Ry2[rr]  = Bv.w;
        Rw[rr]   = Cv.x; Rh[rr]   = Cv.y; Ra[rr]   = Cv.z;
    }

    const float* prow = g_prob + (size_t)(r0 + rloc) * NC_;

    float res[4][4];

    #pragma unroll
    for (int cc = 0; cc < 4; cc++) {
        const int si = SIDX(cloc + cc);
        const float4 A  = scA[si];   // 5*norm coords
        const float4 Bv = scB[si];   // xyxy
        const float4 Cv = scC[si];   // w,h,area,clsbits
        const float cnx1 = A.x,  cny1 = A.y,  cnx2 = A.z,  cny2 = A.w;
        const float ctx1 = Bv.x, cty1 = Bv.y, ctx2 = Bv.z, cty2 = Bv.w;
        const float cwt  = Cv.x, cht  = Cv.y, cat  = Cv.z;
        const int   cls  = __float_as_int(Cv.w);

        #pragma unroll
        for (int rr = 0; rr < 4; rr++) {
            // intersection extents (FMNMX -> alu pipe)
            float m2x = fminf(Rx2[rr], ctx2);
            float M1x = fmaxf(Rx1[rr], ctx1);
            float m2y = fminf(Ry2[rr], cty2);
            float M1y = fmaxf(Ry1[rr], cty1);
            float wrx = fsub1(m2x, M1x);
            float wry = fsub1(m2y, M1y);
            float iw  = fmaxf(wrx, 0.f);
            float ih  = fmaxf(wry, 0.f);
            // enclosing extents via max = sum - min identity
            float exs = fsub1(fadd1(Rw[rr], cwt), wrx);
            float eys = fsub1(fadd1(Rh[rr], cht), wry);
            float inter = iw * ih;
            float areae = exs * eys;
            float uni   = fsub1(fadd1(Ra[rr], cat), inter);
            // giou terms with single fast division
            float num = fmaf(inter, areae, uni * uni);
            float den = uni * areae;

            // 5*L1 of normalized boxes (coords pre-scaled by 5)
            float d1 = fsub1(Rnx1[rr], cnx1);
            float d2 = fsub1(Rny1[rr], cny1);
            float d3 = fsub1(Rnx2[rr], cnx2);
            float d4 = fsub1(Rny2[rr], cny2);
            float s1 = fabsf(d1) + fabsf(d2);
            float s2 = fabsf(d3) + fabsf(d4);
            float cb = fadd1(s1, s2);

            // pv = 2 - 2*p  (one LDG, all lanes on the same L1-resident row)
            float pv = __ldg(&prow[rr * NC_ + cls]);

            // C = cb + pv - 2*(num/den)
            float base = fadd1(cb, pv);
            res[rr][cc] = fnma2(__fdividef(num, den), base);
        }
    }

    // Coalesced float4 stores (warp covers 512B contiguous per rr)
    #pragma unroll
    for (int rr = 0; rr < 4; rr++) {
        size_t i = (size_t)(r0 + rloc + rr);
        float4 v = make_float4(res[rr][0], res[rr][1], res[rr][2], res[rr][3]);
        *reinterpret_cast<float4*>(out + i * BT_ + c0 + cloc) = v;
    }
}

// ---------------------------------------------------------------------------
extern "C" void kernel_launch(void* const* d_in, const int* in_sizes, int n_in,
                              void* d_out, int out_size)
{
    const float* pred_logits  = (const float*)d_in[0];   // [B,Q,NC]
    const float* pred_boxes   = (const float*)d_in[1];   // [B,Q,4]
    const int*   tgt_labels   = (const int*)d_in[2];     // [B,T]
    const float* tgt_boxes    = (const float*)d_in[3];   // [B,T,4]
    const float* img_sz       = (const float*)d_in[4];   // [B,4]
    const float* img_sz_tgt   = (const float*)d_in[5];   // [B,T,4]
    float* out = (float*)d_out;

    prep_kernel<<<ROWBLKS + (BT_ + 255) / 256, 256>>>(
        pred_logits, pred_boxes, img_sz, tgt_boxes, tgt_labels, img_sz_tgt);

    dim3 grid(BT_ / TC, BQ_ / TR);   // (32, 500)
    cost_kernel<<<grid, 256>>>(out);
}